// round 5
// baseline (speedup 1.0000x reference)
#include <cuda_runtime.h>
#include <math.h>

// Problem constants
#define NIMG 512          // B*C
#define NALL 1024         // pred + gt images

// Output offsets (tuple order, flattened)
#define OFF_E    0
#define OFF_U    524288
#define OFF_F    1048576
#define OFF_W    1572864
#define OFF_US   2097152
#define OFF_ES   2098176
#define OFF_ERR  2099200
#define OFF_CAL  2623488

// ---------------------------------------------------------------------------
// Compile-time twiddle table: cos/sin(2*pi*m/256) as float literals so the
// fully-unrolled DFT loops become FFMA-with-immediate (rt_SMSP=1 on sm_10x).
// ---------------------------------------------------------------------------
struct Tw { float c[256]; float s[256]; };

__host__ __device__ constexpr double k_cpi_taylor(double x) {  // cos(x)
    double term = 1.0, sum = 1.0, x2 = x * x;
    for (int j = 1; j <= 14; j++) { term *= -x2 / double((2*j-1)*(2*j)); sum += term; }
    return sum;
}
__host__ __device__ constexpr double k_cos256(int m) {         // cos(2*pi*m/256)
    m &= 255;
    if (m > 128) m = 256 - m;
    constexpr double PI = 3.14159265358979323846;
    if (m <= 64) return  k_cpi_taylor(PI * (double)m / 128.0);
    return -k_cpi_taylor(PI * (double)(128 - m) / 128.0);
}
__host__ __device__ constexpr Tw k_mktw() {
    Tw t{};
    for (int m = 0; m < 256; m++) {
        t.c[m] = (float)k_cos256(m);
        t.s[m] = (float)k_cos256(m + 192);   // sin(th) = cos(th - pi/2)
    }
    return t;
}
__device__ constexpr Tw TW = k_mktw();

// Scratch: only the tiny modes array remains global.
__device__ float g_modes[(size_t)NALL * 2048];   // per image: [re 0..1023 | im 0..1023]

// ---------------------------------------------------------------------------
// K1 smem layout (floats):
//   fold buffers (stage A, 32-row chunks): 4 x [n 0..63][r 0..31] stride 33
//   sT: [c 0..63][row 0..255], XOR-swizzled: addr = c*256 + (row ^ (c&31))
//   sRA/sRB (stage B results, reuse fold area): [c 0..63][k1 0..31] stride 33
// ---------------------------------------------------------------------------
#define F_CE 0
#define F_CO 2112
#define F_SE 4224
#define F_SO 6336
#define OT   8448
#define K1_FLOATS 24832          // 99328 bytes -> 2 CTAs/SM
#define RA 0
#define RB 2112

// Fold phase: double fold of one 32-row chunk into the 4 source arrays.
__device__ __forceinline__ void foldA(float* sm, const float* src, int tid, int q)
{
    const float* rows = src + q * 32 * 256;
    const int n = tid & 63;
    const int rbase = tid >> 6;          // 0..3
#pragma unroll
    for (int it = 0; it < 8; it++) {
        int r = rbase + it * 4;
        const float* row = rows + r * 256;
        if (n == 0) {
            sm[F_CE + r] = row[0];
            sm[F_CO + r] = row[128];
            float a = row[64], b = row[192];
            sm[F_SE + r] = a + b;
            sm[F_SO + r] = a - b;
        } else {
            float a = row[n], b = row[256 - n], e = row[128 - n], d = row[128 + n];
            sm[F_CE + n * 33 + r] = (a + b) + (e + d);
            sm[F_CO + n * 33 + r] = (a + b) - (e + d);
            sm[F_SE + n * 33 + r] = (a - b) - (e - d);
            sm[F_SO + n * 33 + r] = (a - b) + (e - d);
        }
    }
}

// Stage A compute: warp = (parity P, j-group JG); thread = row lane.
// All twiddle indices compile-time -> FFMA immediates.
template<int P, int JG>
__device__ __forceinline__ void stageA_compute(const float* sm, float* sT, int lane, int q)
{
    const float* fc = sm + (P ? F_CO : F_CE);
    const float* fs = sm + (P ? F_SO : F_SE);
    float accC[4] = {0.f, 0.f, 0.f, 0.f};
    float accS[4] = {0.f, 0.f, 0.f, 0.f};
#pragma unroll
    for (int n = 1; n < 64; n++) {
        float cu = fc[n * 33 + lane];
        float sv = fs[n * 33 + lane];
#pragma unroll
        for (int jj = 0; jj < 4; jj++) {
            const int k = 2 * (JG * 4 + jj) + P;
            accC[jj] = fmaf(cu, TW.c[(n * k) & 255], accC[jj]);
            if (k > 0) accS[jj] = fmaf(sv, TW.s[(n * k) & 255], accS[jj]);
        }
    }
    float x0 = sm[F_CE + lane], x128 = sm[F_CO + lane];
    float u64v = sm[F_SE + lane], v64v = sm[F_SO + lane];
#pragma unroll
    for (int jj = 0; jj < 4; jj++) {
        const int j = JG * 4 + jj;
        if (P == 0) {
            accC[jj] += x0 + x128 + ((j & 1) ? -u64v : u64v);
        } else {
            accC[jj] += x0 - x128;
            accS[jj] += (j & 1) ? -v64v : v64v;
        }
    }
    const int row = q * 32 + lane;
#pragma unroll
    for (int jj = 0; jj < 4; jj++) {
        const int k = 2 * (JG * 4 + jj) + P;
        sT[k * 256 + (row ^ (k & 31))]        = accC[jj];
        sT[(32 + k) * 256 + (row ^ (k & 31))] = accS[jj];
    }
}

// Stage B compute: warp = (P, j-half JH, column-group); folds the 256-row
// column of sT on the fly (double fold), 8 k1 outputs per thread.
template<int P, int JH>
__device__ __forceinline__ void stageB_compute(const float* sT, float* sm, int c)
{
    const int cb = c & 31;
    const float* col = sT + c * 256;
    float aA[8] = {0.f,0.f,0.f,0.f,0.f,0.f,0.f,0.f};
    float aB[8] = {0.f,0.f,0.f,0.f,0.f,0.f,0.f,0.f};
#pragma unroll
    for (int n = 1; n < 64; n++) {
        float a = col[n ^ cb];
        float b = col[(256 - n) ^ cb];
        float e = col[(128 - n) ^ cb];
        float d = col[(128 + n) ^ cb];
        float cs, ss;
        if (P == 0) { cs = (a + b) + (e + d); ss = (a - b) - (e - d); }
        else        { cs = (a + b) - (e + d); ss = (a - b) + (e - d); }
#pragma unroll
        for (int jj = 0; jj < 8; jj++) {
            const int k = 2 * (JH * 8 + jj) + P;
            aA[jj] = fmaf(cs, TW.c[(n * k) & 255], aA[jj]);
            if (k > 0) aB[jj] = fmaf(ss, TW.s[(n * k) & 255], aB[jj]);
        }
    }
    float s0 = col[0 ^ cb], s64 = col[64 ^ cb];
    float s128 = col[128 ^ cb], s192 = col[192 ^ cb];
#pragma unroll
    for (int jj = 0; jj < 8; jj++) {
        const int j = JH * 8 + jj;
        const int k = 2 * j + P;
        if (P == 0) {
            float pe = s64 + s192;
            aA[jj] += s0 + s128 + ((j & 1) ? -pe : pe);
        } else {
            float po = s64 - s192;
            aA[jj] += s0 - s128;
            aB[jj] += (j & 1) ? -po : po;
        }
        sm[RA + c * 33 + k] = aA[jj];
        sm[RB + c * 33 + k] = aB[jj];
    }
}

// ---------------------------------------------------------------------------
// K1: fused rfft2 (stage A + stage B in one CTA).  CTA = one image.
// ---------------------------------------------------------------------------
__global__ __launch_bounds__(256) void k_rfft2(const float* __restrict__ pred,
                                               const float* __restrict__ gt)
{
    extern __shared__ float sm[];
    float* sT = sm + OT;

    const int img = blockIdx.x;
    const float* src = (img < NIMG) ? pred + (size_t)img * 65536
                                    : gt   + (size_t)(img - NIMG) * 65536;
    const int tid  = threadIdx.x;
    const int wid  = tid >> 5;
    const int lane = tid & 31;

    // Stage A: 8 chunks of 32 rows.
#pragma unroll 1
    for (int q = 0; q < 8; q++) {
        if (q) __syncthreads();          // fold buffers free again
        foldA(sm, src, tid, q);
        __syncthreads();
        switch (wid) {
            case 0: stageA_compute<0, 0>(sm, sT, lane, q); break;
            case 1: stageA_compute<1, 0>(sm, sT, lane, q); break;
            case 2: stageA_compute<0, 1>(sm, sT, lane, q); break;
            case 3: stageA_compute<1, 1>(sm, sT, lane, q); break;
            case 4: stageA_compute<0, 2>(sm, sT, lane, q); break;
            case 5: stageA_compute<1, 2>(sm, sT, lane, q); break;
            case 6: stageA_compute<0, 3>(sm, sT, lane, q); break;
            case 7: stageA_compute<1, 3>(sm, sT, lane, q); break;
        }
    }
    __syncthreads();                     // sT complete; fold area free for sR

    // Stage B: fold-on-the-fly column DFT of sT.
    {
        const int c = (wid >> 2) * 32 + lane;
        switch (wid & 3) {
            case 0: stageB_compute<0, 0>(sT, sm, c); break;
            case 1: stageB_compute<1, 0>(sT, sm, c); break;
            case 2: stageB_compute<0, 1>(sT, sm, c); break;
            case 3: stageB_compute<1, 1>(sT, sm, c); break;
        }
    }
    __syncthreads();

    // Combine partials into complex modes; write coalesced.
    float* mp = g_modes + (size_t)img * 2048;
#pragma unroll
    for (int t = 0; t < 4; t++) {
        int idx = tid + t * 256;
        int k1 = idx >> 5, k2 = idx & 31;
        float ATc = sm[RA + k2 * 33 + k1];
        float ATs = sm[RA + (32 + k2) * 33 + k1];
        float BTc = sm[RB + k2 * 33 + k1];
        float BTs = sm[RB + (32 + k2) * 33 + k1];
        mp[idx]        = ATc - BTs;
        mp[1024 + idx] = -(BTc + ATs);
    }
}

// ---------------------------------------------------------------------------
// K2: fused MLP + epilogue.  CTA = one pred image: E, ERR, U, in-CTA totalE
// reduction, then F and W.  4 modes per thread in 2 register batches.
// ---------------------------------------------------------------------------
__global__ __launch_bounds__(256) void k_mlp_epi(const float* __restrict__ W1,
                                                 const float* __restrict__ b1,
                                                 const float* __restrict__ W2,
                                                 const float* __restrict__ b2,
                                                 const float* __restrict__ W3,
                                                 const float* __restrict__ b3,
                                                 float* __restrict__ out)
{
    __shared__ float sW1[128], sb1[64], sW2[2048], sb2[32], sW3[32], sb3v;
    __shared__ float sRed[256];
    __shared__ float sTe;
    const int tid = threadIdx.x;
    const int img = blockIdx.x;

    for (int i = tid; i < 128;  i += 256) sW1[i] = W1[i];
    for (int i = tid; i < 2048; i += 256) sW2[i] = W2[i];
    if (tid < 64) sb1[tid] = b1[tid];
    if (tid < 32) { sb2[tid] = b2[tid]; sW3[tid] = W3[tid]; }
    if (tid == 0) sb3v = b3[0];
    __syncthreads();

    const float* mp = g_modes + (size_t)img * 2048;
    const float* mg = g_modes + (size_t)(NIMG + img) * 2048;
    const int base = img * 1024;

    float ev[4], uv[4];
    float eSum = 0.f;

#pragma unroll 1
    for (int bi = 0; bi < 2; bi++) {
        const int i0 = tid + bi * 512;
        const int i1 = i0 + 256;
        float pr0 = mp[i0], pi0 = mp[1024 + i0];
        float pr1 = mp[i1], pi1 = mp[1024 + i1];
        float gr0 = mg[i0], gi0 = mg[1024 + i0];
        float gr1 = mg[i1], gi1 = mg[1024 + i1];

        float E0 = fmaf(pr0, pr0, pi0 * pi0);
        float E1 = fmaf(pr1, pr1, pi1 * pi1);
        out[OFF_E + base + i0] = E0;
        out[OFF_E + base + i1] = E1;
        float d0r = pr0 - gr0, d0i = pi0 - gi0;
        float d1r = pr1 - gr1, d1i = pi1 - gi1;
        out[OFF_ERR + base + i0] = fmaf(d0r, d0r, d0i * d0i);
        out[OFF_ERR + base + i1] = fmaf(d1r, d1r, d1i * d1i);
        ev[bi * 2] = E0; ev[bi * 2 + 1] = E1;
        eSum += E0 + E1;

        float h2a[32], h2b[32];
#pragma unroll
        for (int j = 0; j < 32; j++) { h2a[j] = sb2[j]; h2b[j] = sb2[j]; }

#pragma unroll 8
        for (int i = 0; i < 64; i++) {
            float w1a = sW1[i], w1b = sW1[64 + i], bb = sb1[i];
            float a0 = fmaf(pr0, w1a, fmaf(pi0, w1b, bb));
            float a1 = fmaf(pr1, w1a, fmaf(pi1, w1b, bb));
            a0 = a0 > 0.f ? a0 : 0.f;
            a1 = a1 > 0.f ? a1 : 0.f;
            const float4* w4 = (const float4*)(sW2 + i * 32);
#pragma unroll
            for (int qq = 0; qq < 8; qq++) {
                float4 w = w4[qq];
                h2a[qq*4+0] = fmaf(a0, w.x, h2a[qq*4+0]);
                h2a[qq*4+1] = fmaf(a0, w.y, h2a[qq*4+1]);
                h2a[qq*4+2] = fmaf(a0, w.z, h2a[qq*4+2]);
                h2a[qq*4+3] = fmaf(a0, w.w, h2a[qq*4+3]);
                h2b[qq*4+0] = fmaf(a1, w.x, h2b[qq*4+0]);
                h2b[qq*4+1] = fmaf(a1, w.y, h2b[qq*4+1]);
                h2b[qq*4+2] = fmaf(a1, w.z, h2b[qq*4+2]);
                h2b[qq*4+3] = fmaf(a1, w.w, h2b[qq*4+3]);
            }
        }
        float o0 = sb3v, o1 = sb3v;
#pragma unroll
        for (int j = 0; j < 32; j++) {
            float va = h2a[j] > 0.f ? h2a[j] : 0.f;
            float vb = h2b[j] > 0.f ? h2b[j] : 0.f;
            o0 = fmaf(va, sW3[j], o0);
            o1 = fmaf(vb, sW3[j], o1);
        }
        float u0 = fmaxf(o0, 0.f) + log1pf(expf(-fabsf(o0)));
        float u1 = fmaxf(o1, 0.f) + log1pf(expf(-fabsf(o1)));
        out[OFF_U + base + i0] = u0;
        out[OFF_U + base + i1] = u1;
        uv[bi * 2] = u0; uv[bi * 2 + 1] = u1;
    }

    // In-CTA total modal energy reduction.
    sRed[tid] = eSum;
    __syncthreads();
    for (int w = 128; w > 0; w >>= 1) {
        if (tid < w) sRed[tid] += sRed[tid + w];
        __syncthreads();
    }
    if (tid == 0) sTe = sRed[0];
    __syncthreads();
    const float te = sTe + 1e-8f;

#pragma unroll
    for (int b = 0; b < 4; b++) {
        int idx = tid + b * 256;
        float F = ev[b] / te;
        out[OFF_F + base + idx] = F;
        out[OFF_W + base + idx] = F * uv[b];
    }
}

// ---------------------------------------------------------------------------
// K3: per-mode stats.  128 CTAs x 256 thr; fp64 accumulators, tree reduce.
// ---------------------------------------------------------------------------
__global__ __launch_bounds__(256) void k_stats(float* __restrict__ out)
{
    __shared__ double red[6][256];
    const int tid = threadIdx.x;
    const int kl  = tid & 7;
    const int sg  = tid >> 3;                 // 0..31
    const int k   = blockIdx.x * 8 + kl;

    double su = 0, se = 0, sen = 0, sue = 0, suu = 0, see = 0;
    for (int s = sg; s < NIMG; s += 32) {
        float u  = out[OFF_U   + (size_t)s * 1024 + k];
        float e  = out[OFF_ERR + (size_t)s * 1024 + k];
        float en = out[OFF_E   + (size_t)s * 1024 + k];
        su += u; se += e; sen += en;
        sue += (double)u * (double)e;
        suu += (double)u * (double)u;
        see += (double)e * (double)e;
    }
    red[0][tid] = su;  red[1][tid] = se;  red[2][tid] = sen;
    red[3][tid] = sue; red[4][tid] = suu; red[5][tid] = see;
    __syncthreads();

    for (int off = 16; off >= 1; off >>= 1) {
        if (sg < off) {
#pragma unroll
            for (int m = 0; m < 6; m++)
                red[m][tid] += red[m][tid + off * 8];
        }
        __syncthreads();
    }
    if (tid < 8) {
        double tsu = red[0][tid], tse = red[1][tid], tsen = red[2][tid];
        double tsue = red[3][tid], tsuu = red[4][tid], tsee = red[5][tid];
        out[OFF_US + k] = (float)(tsu  * (1.0 / 512.0));
        out[OFF_ES + k] = (float)(tsen * (1.0 / 512.0));
        double num  = tsue - tsu * tse * (1.0 / 512.0);
        double varu = tsuu - tsu * tsu * (1.0 / 512.0);
        double vare = tsee - tse * tse * (1.0 / 512.0);
        out[OFF_CAL + k] = (float)(num / (sqrt(varu * vare) + 1e-8));
    }
}

// ---------------------------------------------------------------------------
extern "C" void kernel_launch(void* const* d_in, const int* in_sizes, int n_in,
                              void* d_out, int out_size)
{
    const float* pred = (const float*)d_in[0];
    // d_in[1] = uncertainty: unused by the reference
    const float* gt   = (const float*)d_in[2];
    const float* W1   = (const float*)d_in[3];
    const float* b1   = (const float*)d_in[4];
    const float* W2   = (const float*)d_in[5];
    const float* b2   = (const float*)d_in[6];
    const float* W3   = (const float*)d_in[7];
    const float* b3   = (const float*)d_in[8];
    float* out = (float*)d_out;

    const int smem1 = K1_FLOATS * 4;   // 99328 B
    cudaFuncSetAttribute(k_rfft2, cudaFuncAttributeMaxDynamicSharedMemorySize, smem1);

    k_rfft2<<<1024, 256, smem1>>>(pred, gt);
    k_mlp_epi<<<512, 256>>>(W1, b1, W2, b2, W3, b3, out);
    k_stats<<<128, 256>>>(out);
}

// round 7
// speedup vs baseline: 1.2119x; 1.2119x over previous
#include <cuda_runtime.h>
#include <math.h>

// Problem constants
#define NIMG 512          // B*C
#define NALL 1024         // pred + gt images

// Output offsets (tuple order, flattened)
#define OFF_E    0
#define OFF_U    524288
#define OFF_F    1048576
#define OFF_W    1572864
#define OFF_US   2097152
#define OFF_ES   2098176
#define OFF_ERR  2099200
#define OFF_CAL  2623488

// ---------------------------------------------------------------------------
// Compile-time twiddles.  k_cos256(m) = cos(2*pi*m/256), constexpr.
// Used ONLY with template-parameter arguments so every twiddle is a local
// constexpr float -> a literal in PTX -> FFMA-with-immediate in SASS (rt=1).
// ---------------------------------------------------------------------------
__host__ __device__ constexpr double k_cpi_taylor(double x) {  // cos(x)
    double term = 1.0, sum = 1.0, x2 = x * x;
    for (int j = 1; j <= 14; j++) { term *= -x2 / double((2*j-1)*(2*j)); sum += term; }
    return sum;
}
__host__ __device__ constexpr double k_cos256(int m) {         // cos(2*pi*m/256)
    m &= 255;
    if (m > 128) m = 256 - m;
    constexpr double PI = 3.14159265358979323846;
    if (m <= 64) return  k_cpi_taylor(PI * (double)m / 128.0);
    return -k_cpi_taylor(PI * (double)(128 - m) / 128.0);
}

// Scratch: only the tiny modes array is global.
__device__ float g_modes[(size_t)NALL * 2048];   // per image: [re 0..1023 | im 0..1023]

// ---------------------------------------------------------------------------
// K1 smem layout (floats):
//   fold buffers: 4 x [n 0..63][r 0..31] stride 33
//   sT: [c 0..63][row 0..255], XOR swizzle addr = c*256 + (row ^ (c&31))
//   sRA/sRB (stage B results, reuse fold area): [c][k1] stride 33
// ---------------------------------------------------------------------------
#define F_CE 0
#define F_CO 2112
#define F_SE 4224
#define F_SO 6336
#define OT   8448
#define K1_FLOATS 24832          // 99328 bytes -> 2 CTAs/SM
#define RA 0
#define RB 2112

// ---------------------------------------------------------------------------
// Stage A inner machinery: literal-twiddle FMA steps via template recursion.
// ---------------------------------------------------------------------------
template<int P, int JG, int N, int JJ> struct FmaJ {
    static __device__ __forceinline__ void f(float cu, float sv,
                                             float (&aC)[4], float (&aS)[4]) {
        constexpr int   K  = 2 * (JG * 4 + JJ) + P;
        constexpr float cc = (float)k_cos256(N * K);
        aC[JJ] = fmaf(cu, cc, aC[JJ]);
        if constexpr (K > 0) {
            constexpr float ss = (float)k_cos256(N * K + 192);   // sin
            aS[JJ] = fmaf(sv, ss, aS[JJ]);
        }
    }
};

template<int P, int JG, int N> struct AStep {
    static __device__ __forceinline__ void run(const float* fc, const float* fs, int lane,
                                               float (&aC)[4], float (&aS)[4]) {
        const float cu = fc[N * 33 + lane];
        const float sv = fs[N * 33 + lane];
        FmaJ<P, JG, N, 0>::f(cu, sv, aC, aS);
        FmaJ<P, JG, N, 1>::f(cu, sv, aC, aS);
        FmaJ<P, JG, N, 2>::f(cu, sv, aC, aS);
        FmaJ<P, JG, N, 3>::f(cu, sv, aC, aS);
        AStep<P, JG, N + 1>::run(fc, fs, lane, aC, aS);
    }
};
template<int P, int JG> struct AStep<P, JG, 64> {
    static __device__ __forceinline__ void run(const float*, const float*, int,
                                               float (&)[4], float (&)[4]) {}
};

// Stage A compute: warp = (parity P, j-group JG); thread = row lane.
template<int P, int JG>
__device__ __forceinline__ void stageA_compute(const float* sm, float* sT, int lane, int q)
{
    const float* fc = sm + (P ? F_CO : F_CE);
    const float* fs = sm + (P ? F_SO : F_SE);
    float accC[4] = {0.f, 0.f, 0.f, 0.f};
    float accS[4] = {0.f, 0.f, 0.f, 0.f};

    AStep<P, JG, 1>::run(fc, fs, lane, accC, accS);

    float x0 = sm[F_CE + lane], x128 = sm[F_CO + lane];
    float u64v = sm[F_SE + lane], v64v = sm[F_SO + lane];
#pragma unroll
    for (int jj = 0; jj < 4; jj++) {
        const int j = JG * 4 + jj;
        if (P == 0) {
            accC[jj] += x0 + x128 + ((j & 1) ? -u64v : u64v);
        } else {
            accC[jj] += x0 - x128;
            accS[jj] += (j & 1) ? -v64v : v64v;
        }
    }
    const int row = q * 32 + lane;
#pragma unroll
    for (int jj = 0; jj < 4; jj++) {
        const int k = 2 * (JG * 4 + jj) + P;
        sT[k * 256 + (row ^ (k & 31))]        = accC[jj];
        sT[(32 + k) * 256 + (row ^ (k & 31))] = accS[jj];
    }
}

// ---------------------------------------------------------------------------
// Stage B inner machinery (same literal-twiddle trick).
// ---------------------------------------------------------------------------
template<int P, int JH, int N, int JJ> struct BFma {
    static __device__ __forceinline__ void f(float cs, float ss,
                                             float (&aA)[8], float (&aB)[8]) {
        constexpr int   K  = 2 * (JH * 8 + JJ) + P;
        constexpr float cc = (float)k_cos256(N * K);
        aA[JJ] = fmaf(cs, cc, aA[JJ]);
        if constexpr (K > 0) {
            constexpr float sn = (float)k_cos256(N * K + 192);
            aB[JJ] = fmaf(ss, sn, aB[JJ]);
        }
    }
};

template<int P, int JH, int N> struct BStep {
    static __device__ __forceinline__ void run(const float* col, int cb,
                                               float (&aA)[8], float (&aB)[8]) {
        float a = col[N ^ cb];
        float b = col[(256 - N) ^ cb];
        float e = col[(128 - N) ^ cb];
        float d = col[(128 + N) ^ cb];
        float cs, ss;
        if constexpr (P == 0) { cs = (a + b) + (e + d); ss = (a - b) - (e - d); }
        else                  { cs = (a + b) - (e + d); ss = (a - b) + (e - d); }
        BFma<P, JH, N, 0>::f(cs, ss, aA, aB);
        BFma<P, JH, N, 1>::f(cs, ss, aA, aB);
        BFma<P, JH, N, 2>::f(cs, ss, aA, aB);
        BFma<P, JH, N, 3>::f(cs, ss, aA, aB);
        BFma<P, JH, N, 4>::f(cs, ss, aA, aB);
        BFma<P, JH, N, 5>::f(cs, ss, aA, aB);
        BFma<P, JH, N, 6>::f(cs, ss, aA, aB);
        BFma<P, JH, N, 7>::f(cs, ss, aA, aB);
        BStep<P, JH, N + 1>::run(col, cb, aA, aB);
    }
};
template<int P, int JH> struct BStep<P, JH, 64> {
    static __device__ __forceinline__ void run(const float*, int,
                                               float (&)[8], float (&)[8]) {}
};

template<int P, int JH>
__device__ __forceinline__ void stageB_compute(const float* sT, float* sm, int c)
{
    const int cb = c & 31;
    const float* col = sT + c * 256;
    float aA[8] = {0.f,0.f,0.f,0.f,0.f,0.f,0.f,0.f};
    float aB[8] = {0.f,0.f,0.f,0.f,0.f,0.f,0.f,0.f};

    BStep<P, JH, 1>::run(col, cb, aA, aB);

    float s0 = col[0 ^ cb], s64 = col[64 ^ cb];
    float s128 = col[128 ^ cb], s192 = col[192 ^ cb];
#pragma unroll
    for (int jj = 0; jj < 8; jj++) {
        const int j = JH * 8 + jj;
        const int k = 2 * j + P;
        if (P == 0) {
            float pe = s64 + s192;
            aA[jj] += s0 + s128 + ((j & 1) ? -pe : pe);
        } else {
            float po = s64 - s192;
            aA[jj] += s0 - s128;
            aB[jj] += (j & 1) ? -po : po;
        }
        sm[RA + c * 33 + k] = aA[jj];
        sm[RB + c * 33 + k] = aB[jj];
    }
}

// ---------------------------------------------------------------------------
// Fold phase split into load (gmem -> regs) and store (fold arith -> smem)
// so chunk q+1's loads overlap chunk q's compute.
// ---------------------------------------------------------------------------
__device__ __forceinline__ void loadA(float (&v)[32], const float* src, int tid, int q)
{
    const float* rows = src + q * 32 * 256;
    const int n = tid & 63;
    const int rbase = tid >> 6;
#pragma unroll
    for (int it = 0; it < 8; it++) {
        const float* row = rows + (rbase + it * 4) * 256;
        if (n == 0) {
            v[it*4+0] = row[0];   v[it*4+1] = row[128];
            v[it*4+2] = row[64];  v[it*4+3] = row[192];
        } else {
            v[it*4+0] = row[n];        v[it*4+1] = row[256 - n];
            v[it*4+2] = row[128 - n];  v[it*4+3] = row[128 + n];
        }
    }
}

__device__ __forceinline__ void storeA(float* sm, const float (&v)[32], int tid)
{
    const int n = tid & 63;
    const int rbase = tid >> 6;
#pragma unroll
    for (int it = 0; it < 8; it++) {
        const int r = rbase + it * 4;
        float a = v[it*4+0], b = v[it*4+1], e = v[it*4+2], d = v[it*4+3];
        if (n == 0) {
            sm[F_CE + r] = a;
            sm[F_CO + r] = b;
            sm[F_SE + r] = e + d;
            sm[F_SO + r] = e - d;
        } else {
            sm[F_CE + n * 33 + r] = (a + b) + (e + d);
            sm[F_CO + n * 33 + r] = (a + b) - (e + d);
            sm[F_SE + n * 33 + r] = (a - b) - (e - d);
            sm[F_SO + n * 33 + r] = (a - b) + (e - d);
        }
    }
}

// ---------------------------------------------------------------------------
// K1: fused rfft2.  CTA = one image.  Pipelined stage A + in-smem stage B.
// ---------------------------------------------------------------------------
__global__ __launch_bounds__(256) void k_rfft2(const float* __restrict__ pred,
                                               const float* __restrict__ gt)
{
    extern __shared__ float sm[];
    float* sT = sm + OT;

    const int img = blockIdx.x;
    const float* src = (img < NIMG) ? pred + (size_t)img * 65536
                                    : gt   + (size_t)(img - NIMG) * 65536;
    const int tid  = threadIdx.x;
    const int wid  = tid >> 5;
    const int lane = tid & 31;

    float v[32];
    loadA(v, src, tid, 0);

#pragma unroll 1
    for (int q = 0; q < 8; q++) {
        storeA(sm, v, tid);
        __syncthreads();
        if (q < 7) loadA(v, src, tid, q + 1);   // overlap with compute below
        switch (wid) {
            case 0: stageA_compute<0, 0>(sm, sT, lane, q); break;
            case 1: stageA_compute<1, 0>(sm, sT, lane, q); break;
            case 2: stageA_compute<0, 1>(sm, sT, lane, q); break;
            case 3: stageA_compute<1, 1>(sm, sT, lane, q); break;
            case 4: stageA_compute<0, 2>(sm, sT, lane, q); break;
            case 5: stageA_compute<1, 2>(sm, sT, lane, q); break;
            case 6: stageA_compute<0, 3>(sm, sT, lane, q); break;
            case 7: stageA_compute<1, 3>(sm, sT, lane, q); break;
        }
        __syncthreads();
    }

    // Stage B: fold-on-the-fly column DFT of sT (results into fold area).
    {
        const int c = (wid >> 2) * 32 + lane;
        switch (wid & 3) {
            case 0: stageB_compute<0, 0>(sT, sm, c); break;
            case 1: stageB_compute<1, 0>(sT, sm, c); break;
            case 2: stageB_compute<0, 1>(sT, sm, c); break;
            case 3: stageB_compute<1, 1>(sT, sm, c); break;
        }
    }
    __syncthreads();

    // Combine partials into complex modes; coalesced writes.
    float* mp = g_modes + (size_t)img * 2048;
#pragma unroll
    for (int t = 0; t < 4; t++) {
        int idx = tid + t * 256;
        int k1 = idx >> 5, k2 = idx & 31;
        float ATc = sm[RA + k2 * 33 + k1];
        float ATs = sm[RA + (32 + k2) * 33 + k1];
        float BTc = sm[RB + k2 * 33 + k1];
        float BTs = sm[RB + (32 + k2) * 33 + k1];
        mp[idx]        = ATc - BTs;
        mp[1024 + idx] = -(BTc + ATs);
    }
}

// ---------------------------------------------------------------------------
// K2: fused MLP + epilogue.
// ---------------------------------------------------------------------------
__global__ __launch_bounds__(256) void k_mlp_epi(const float* __restrict__ W1,
                                                 const float* __restrict__ b1,
                                                 const float* __restrict__ W2,
                                                 const float* __restrict__ b2,
                                                 const float* __restrict__ W3,
                                                 const float* __restrict__ b3,
                                                 float* __restrict__ out)
{
    __shared__ float sW1[128], sb1[64], sW2[2048], sb2[32], sW3[32], sb3v;
    __shared__ float sRed[256];
    __shared__ float sTe;
    const int tid = threadIdx.x;
    const int img = blockIdx.x;

    for (int i = tid; i < 128;  i += 256) sW1[i] = W1[i];
    for (int i = tid; i < 2048; i += 256) sW2[i] = W2[i];
    if (tid < 64) sb1[tid] = b1[tid];
    if (tid < 32) { sb2[tid] = b2[tid]; sW3[tid] = W3[tid]; }
    if (tid == 0) sb3v = b3[0];
    __syncthreads();

    const float* mp = g_modes + (size_t)img * 2048;
    const float* mg = g_modes + (size_t)(NIMG + img) * 2048;
    const int base = img * 1024;

    float ev[4], uv[4];
    float eSum = 0.f;

#pragma unroll 1
    for (int bi = 0; bi < 2; bi++) {
        const int i0 = tid + bi * 512;
        const int i1 = i0 + 256;
        float pr0 = mp[i0], pi0 = mp[1024 + i0];
        float pr1 = mp[i1], pi1 = mp[1024 + i1];
        float gr0 = mg[i0], gi0 = mg[1024 + i0];
        float gr1 = mg[i1], gi1 = mg[1024 + i1];

        float E0 = fmaf(pr0, pr0, pi0 * pi0);
        float E1 = fmaf(pr1, pr1, pi1 * pi1);
        out[OFF_E + base + i0] = E0;
        out[OFF_E + base + i1] = E1;
        float d0r = pr0 - gr0, d0i = pi0 - gi0;
        float d1r = pr1 - gr1, d1i = pi1 - gi1;
        out[OFF_ERR + base + i0] = fmaf(d0r, d0r, d0i * d0i);
        out[OFF_ERR + base + i1] = fmaf(d1r, d1r, d1i * d1i);
        ev[bi * 2] = E0; ev[bi * 2 + 1] = E1;
        eSum += E0 + E1;

        float h2a[32], h2b[32];
#pragma unroll
        for (int j = 0; j < 32; j++) { h2a[j] = sb2[j]; h2b[j] = sb2[j]; }

#pragma unroll 8
        for (int i = 0; i < 64; i++) {
            float w1a = sW1[i], w1b = sW1[64 + i], bb = sb1[i];
            float a0 = fmaf(pr0, w1a, fmaf(pi0, w1b, bb));
            float a1 = fmaf(pr1, w1a, fmaf(pi1, w1b, bb));
            a0 = a0 > 0.f ? a0 : 0.f;
            a1 = a1 > 0.f ? a1 : 0.f;
            const float4* w4 = (const float4*)(sW2 + i * 32);
#pragma unroll
            for (int qq = 0; qq < 8; qq++) {
                float4 w = w4[qq];
                h2a[qq*4+0] = fmaf(a0, w.x, h2a[qq*4+0]);
                h2a[qq*4+1] = fmaf(a0, w.y, h2a[qq*4+1]);
                h2a[qq*4+2] = fmaf(a0, w.z, h2a[qq*4+2]);
                h2a[qq*4+3] = fmaf(a0, w.w, h2a[qq*4+3]);
                h2b[qq*4+0] = fmaf(a1, w.x, h2b[qq*4+0]);
                h2b[qq*4+1] = fmaf(a1, w.y, h2b[qq*4+1]);
                h2b[qq*4+2] = fmaf(a1, w.z, h2b[qq*4+2]);
                h2b[qq*4+3] = fmaf(a1, w.w, h2b[qq*4+3]);
            }
        }
        float o0 = sb3v, o1 = sb3v;
#pragma unroll
        for (int j = 0; j < 32; j++) {
            float va = h2a[j] > 0.f ? h2a[j] : 0.f;
            float vb = h2b[j] > 0.f ? h2b[j] : 0.f;
            o0 = fmaf(va, sW3[j], o0);
            o1 = fmaf(vb, sW3[j], o1);
        }
        float u0 = fmaxf(o0, 0.f) + log1pf(expf(-fabsf(o0)));
        float u1 = fmaxf(o1, 0.f) + log1pf(expf(-fabsf(o1)));
        out[OFF_U + base + i0] = u0;
        out[OFF_U + base + i1] = u1;
        uv[bi * 2] = u0; uv[bi * 2 + 1] = u1;
    }

    sRed[tid] = eSum;
    __syncthreads();
    for (int w = 128; w > 0; w >>= 1) {
        if (tid < w) sRed[tid] += sRed[tid + w];
        __syncthreads();
    }
    if (tid == 0) sTe = sRed[0];
    __syncthreads();
    const float te = sTe + 1e-8f;

#pragma unroll
    for (int b = 0; b < 4; b++) {
        int idx = tid + b * 256;
        float F = ev[b] / te;
        out[OFF_F + base + idx] = F;
        out[OFF_W + base + idx] = F * uv[b];
    }
}

// ---------------------------------------------------------------------------
// K3: per-mode stats.  128 CTAs x 256 thr; fp64 accumulators, tree reduce.
// ---------------------------------------------------------------------------
__global__ __launch_bounds__(256) void k_stats(float* __restrict__ out)
{
    __shared__ double red[6][256];
    const int tid = threadIdx.x;
    const int kl  = tid & 7;
    const int sg  = tid >> 3;                 // 0..31
    const int k   = blockIdx.x * 8 + kl;

    double su = 0, se = 0, sen = 0, sue = 0, suu = 0, see = 0;
    for (int s = sg; s < NIMG; s += 32) {
        float u  = out[OFF_U   + (size_t)s * 1024 + k];
        float e  = out[OFF_ERR + (size_t)s * 1024 + k];
        float en = out[OFF_E   + (size_t)s * 1024 + k];
        su += u; se += e; sen += en;
        sue += (double)u * (double)e;
        suu += (double)u * (double)u;
        see += (double)e * (double)e;
    }
    red[0][tid] = su;  red[1][tid] = se;  red[2][tid] = sen;
    red[3][tid] = sue; red[4][tid] = suu; red[5][tid] = see;
    __syncthreads();

    for (int off = 16; off >= 1; off >>= 1) {
        if (sg < off) {
#pragma unroll
            for (int m = 0; m < 6; m++)
                red[m][tid] += red[m][tid + off * 8];
        }
        __syncthreads();
    }
    if (tid < 8) {
        double tsu = red[0][tid], tse = red[1][tid], tsen = red[2][tid];
        double tsue = red[3][tid], tsuu = red[4][tid], tsee = red[5][tid];
        out[OFF_US + k] = (float)(tsu  * (1.0 / 512.0));
        out[OFF_ES + k] = (float)(tsen * (1.0 / 512.0));
        double num  = tsue - tsu * tse * (1.0 / 512.0);
        double varu = tsuu - tsu * tsu * (1.0 / 512.0);
        double vare = tsee - tse * tse * (1.0 / 512.0);
        out[OFF_CAL + k] = (float)(num / (sqrt(varu * vare) + 1e-8));
    }
}

// ---------------------------------------------------------------------------
extern "C" void kernel_launch(void* const* d_in, const int* in_sizes, int n_in,
                              void* d_out, int out_size)
{
    const float* pred = (const float*)d_in[0];
    // d_in[1] = uncertainty: unused by the reference
    const float* gt   = (const float*)d_in[2];
    const float* W1   = (const float*)d_in[3];
    const float* b1   = (const float*)d_in[4];
    const float* W2   = (const float*)d_in[5];
    const float* b2   = (const float*)d_in[6];
    const float* W3   = (const float*)d_in[7];
    const float* b3   = (const float*)d_in[8];
    float* out = (float*)d_out;

    const int smem1 = K1_FLOATS * 4;   // 99328 B
    cudaFuncSetAttribute(k_rfft2, cudaFuncAttributeMaxDynamicSharedMemorySize, smem1);

    k_rfft2<<<1024, 256, smem1>>>(pred, gt);
    k_mlp_epi<<<512, 256>>>(W1, b1, W2, b2, W3, b3, out);
    k_stats<<<128, 256>>>(out);
}